// round 1
// baseline (speedup 1.0000x reference)
#include <cuda_runtime.h>
#include <cuda_bf16.h>
#include <cstdio>

// Problem max sizes
#define N_MAX 50000
#define E_MAX 800000
#define H 128

// -------- scratch (device globals; no allocation allowed) --------
__device__ float g_zA[(size_t)N_MAX * H];
__device__ float g_zB[(size_t)N_MAX * H];
__device__ float g_agg[(size_t)N_MAX * H];
__device__ int   g_csr_src[E_MAX];
__device__ int   g_count[N_MAX];
__device__ int   g_cursor[N_MAX];
__device__ int   g_offsets[N_MAX + 1];
__device__ float g_deginv[N_MAX];

// -------- kernels --------

__global__ void zero_kernel(int* count, int* cursor, int n) {
    int i = blockIdx.x * blockDim.x + threadIdx.x;
    if (i < n) { count[i] = 0; cursor[i] = 0; }
}

// z[i] = node_emb[x[i]]  (float4 per thread)
__global__ void gather_kernel(const int* x, const float* node_emb, float* z, int n) {
    int idx = blockIdx.x * blockDim.x + threadIdx.x;  // over n*32 float4s
    if (idx >= n * 32) return;
    int node = idx >> 5;
    int l4   = idx & 31;
    int e = x[node];
    ((float4*)z)[(size_t)node * 32 + l4] = ((const float4*)node_emb)[(size_t)e * 32 + l4];
}

__global__ void count_kernel(const int* row, const int* col, int* count, int E) {
    int e = blockIdx.x * blockDim.x + threadIdx.x;
    if (e >= E) return;
    int r = row[e], c = col[e];
    if (r != c) atomicAdd(&count[c], 1);
}

// single-block exclusive scan over n<=N_MAX; also computes deg_inv
__global__ void scan_kernel(const int* count, int* offsets, float* deg_inv, int n) {
    __shared__ int sdata[1024];
    __shared__ int s_running;
    if (threadIdx.x == 0) s_running = 0;
    __syncthreads();
    for (int base = 0; base < n; base += 1024) {
        int i = base + threadIdx.x;
        int v = (i < n) ? count[i] : 0;
        sdata[threadIdx.x] = v;
        __syncthreads();
        for (int off = 1; off < 1024; off <<= 1) {
            int t = 0;
            if ((int)threadIdx.x >= off) t = sdata[threadIdx.x - off];
            __syncthreads();
            sdata[threadIdx.x] += t;
            __syncthreads();
        }
        int incl = sdata[threadIdx.x];
        int excl = incl - v;
        if (i < n) {
            offsets[i] = s_running + excl;
            deg_inv[i] = 1.0f / (float)(count[i] + 1);
        }
        __syncthreads();
        if (threadIdx.x == 1023) s_running += sdata[1023];
        __syncthreads();
    }
    if (threadIdx.x == 0) offsets[n] = s_running;
}

__global__ void scatter_kernel(const int* row, const int* col, const int* offsets,
                               int* cursor, int* csr_src, int E) {
    int e = blockIdx.x * blockDim.x + threadIdx.x;
    if (e >= E) return;
    int r = row[e], c = col[e];
    if (r != c) {
        int p = atomicAdd(&cursor[c], 1);
        csr_src[offsets[c] + p] = r;
    }
}

// warp per node: agg[c] = deg_inv[c] * (z[c] + sum_{e in csr(c)} z[src[e]])
__global__ void spmm_kernel(const float* __restrict__ z, float* __restrict__ agg,
                            const int* __restrict__ offsets, const int* __restrict__ csr_src,
                            const float* __restrict__ deg_inv, int n) {
    int warp = (blockIdx.x * blockDim.x + threadIdx.x) >> 5;
    int lane = threadIdx.x & 31;
    if (warp >= n) return;
    const float4* z4 = (const float4*)z;
    float4 acc = z4[(size_t)warp * 32 + lane];
    int s = offsets[warp], e = offsets[warp + 1];
    for (int i = s; i < e; i++) {
        int r = csr_src[i];
        float4 v = z4[(size_t)r * 32 + lane];
        acc.x += v.x; acc.y += v.y; acc.z += v.z; acc.w += v.w;
    }
    float di = deg_inv[warp];
    acc.x *= di; acc.y *= di; acc.z *= di; acc.w *= di;
    ((float4*)agg)[(size_t)warp * 32 + lane] = acc;
}

// out = relu(A @ Wout + Z @ Wroot + bias), all H=128. Block = 64 rows, 256 threads.
// SMEM: Wout[128x128] + Wroot[128x128] + A[64x132] + Z[64x132]
#define GEMM_BM 64
#define LDA_S 132
__global__ __launch_bounds__(256, 1)
void gemm_kernel(const float* __restrict__ A, const float* __restrict__ Z,
                 const float* __restrict__ Wout, const float* __restrict__ Wroot,
                 const float* __restrict__ bias, float* __restrict__ out, int n) {
    extern __shared__ float smem[];
    float* Wo = smem;                 // 16384
    float* Wr = smem + 16384;         // 16384
    float* As = smem + 32768;         // 64*132 = 8448
    float* Zs = As + GEMM_BM * LDA_S; // 8448

    int tid = threadIdx.x;
    // load weights (4096 float4 each)
    for (int i = tid; i < 4096; i += 256) {
        ((float4*)Wo)[i] = ((const float4*)Wout)[i];
        ((float4*)Wr)[i] = ((const float4*)Wroot)[i];
    }
    int m0 = blockIdx.x * GEMM_BM;
    // load A,Z tiles (2048 float4 each); pad rows beyond n with zeros
    for (int i = tid; i < 2048; i += 256) {
        int m  = i >> 5;
        int k4 = i & 31;
        float4 av, zv;
        if (m0 + m < n) {
            av = ((const float4*)(A + (size_t)(m0 + m) * H))[k4];
            zv = ((const float4*)(Z + (size_t)(m0 + m) * H))[k4];
        } else {
            av = make_float4(0.f, 0.f, 0.f, 0.f);
            zv = av;
        }
        *(float4*)&As[m * LDA_S + k4 * 4] = av;
        *(float4*)&Zs[m * LDA_S + k4 * 4] = zv;
    }
    __syncthreads();

    int tn = (tid & 15) * 8;   // 16 groups along n
    int tm = (tid >> 4) * 4;   // 16 groups along m

    float acc[4][8];
    #pragma unroll
    for (int i = 0; i < 4; i++)
        #pragma unroll
        for (int j = 0; j < 8; j++) acc[i][j] = 0.f;

    #pragma unroll 4
    for (int k = 0; k < H; k++) {
        float a[4], zz[4];
        #pragma unroll
        for (int i = 0; i < 4; i++) {
            a[i]  = As[(tm + i) * LDA_S + k];
            zz[i] = Zs[(tm + i) * LDA_S + k];
        }
        float4 wo0 = *(float4*)&Wo[k * H + tn];
        float4 wo1 = *(float4*)&Wo[k * H + tn + 4];
        float4 wr0 = *(float4*)&Wr[k * H + tn];
        float4 wr1 = *(float4*)&Wr[k * H + tn + 4];
        #pragma unroll
        for (int i = 0; i < 4; i++) {
            acc[i][0] += a[i] * wo0.x + zz[i] * wr0.x;
            acc[i][1] += a[i] * wo0.y + zz[i] * wr0.y;
            acc[i][2] += a[i] * wo0.z + zz[i] * wr0.z;
            acc[i][3] += a[i] * wo0.w + zz[i] * wr0.w;
            acc[i][4] += a[i] * wo1.x + zz[i] * wr1.x;
            acc[i][5] += a[i] * wo1.y + zz[i] * wr1.y;
            acc[i][6] += a[i] * wo1.z + zz[i] * wr1.z;
            acc[i][7] += a[i] * wo1.w + zz[i] * wr1.w;
        }
    }

    float bv[8];
    #pragma unroll
    for (int j = 0; j < 8; j++) bv[j] = bias[tn + j];
    #pragma unroll
    for (int i = 0; i < 4; i++) {
        int m = m0 + tm + i;
        if (m < n) {
            float4 o0, o1;
            o0.x = fmaxf(acc[i][0] + bv[0], 0.f);
            o0.y = fmaxf(acc[i][1] + bv[1], 0.f);
            o0.z = fmaxf(acc[i][2] + bv[2], 0.f);
            o0.w = fmaxf(acc[i][3] + bv[3], 0.f);
            o1.x = fmaxf(acc[i][4] + bv[4], 0.f);
            o1.y = fmaxf(acc[i][5] + bv[5], 0.f);
            o1.z = fmaxf(acc[i][6] + bv[6], 0.f);
            o1.w = fmaxf(acc[i][7] + bv[7], 0.f);
            *(float4*)&out[(size_t)m * H + tn]     = o0;
            *(float4*)&out[(size_t)m * H + tn + 4] = o1;
        }
    }
}

// MLP head: per row r: ge = [z[r], z[B+r]] (256), h = relu(ge@w1+b1) (128),
// pred = h@w2 + b2. Also writes labels as float.
__global__ __launch_bounds__(128, 1)
void mlp_kernel(const float* __restrict__ z, const int* __restrict__ labels,
                const float* __restrict__ w1, const float* __restrict__ b1,
                const float* __restrict__ w2, const float* __restrict__ b2,
                float* __restrict__ out, int bsz, int out_size) {
    extern __shared__ float smem[];
    float* w1s = smem;          // 256*128
    float* ge  = smem + 32768;  // 256
    __shared__ float red[4];
    int tid = threadIdx.x;      // 128
    for (int i = tid; i < 8192; i += 128)
        ((float4*)w1s)[i] = ((const float4*)w1)[i];
    float b1v = b1[tid];
    float w2v = w2[tid];
    float b2v = b2[0];
    __syncthreads();

    for (int r = blockIdx.x; r < bsz; r += gridDim.x) {
        ge[tid]       = z[(size_t)r * H + tid];
        ge[128 + tid] = z[(size_t)(bsz + r) * H + tid];
        __syncthreads();
        float h = b1v;
        #pragma unroll 8
        for (int k = 0; k < 256; k++)
            h += ge[k] * w1s[k * 128 + tid];
        h = fmaxf(h, 0.f) * w2v;
        #pragma unroll
        for (int off = 16; off; off >>= 1)
            h += __shfl_xor_sync(0xFFFFFFFFu, h, off);
        if ((tid & 31) == 0) red[tid >> 5] = h;
        __syncthreads();
        if (tid == 0) {
            float p = red[0] + red[1] + red[2] + red[3] + b2v;
            out[r] = p;
            if (out_size >= 2 * bsz) out[bsz + r] = (float)labels[r];
        }
        __syncthreads();
    }
}

// -------- host --------
extern "C" void kernel_launch(void* const* d_in, const int* in_sizes, int n_in,
                              void* d_out, int out_size) {
    const int*   x        = (const int*)d_in[0];
    const int*   eidx     = (const int*)d_in[2];
    const int*   labels   = (const int*)d_in[3];
    const float* node_emb = (const float*)d_in[4];
    const float* Wout     = (const float*)d_in[6];
    const float* bout     = (const float*)d_in[7];
    const float* Wroot    = (const float*)d_in[8];
    const float* w1       = (const float*)d_in[9];
    const float* b1       = (const float*)d_in[10];
    const float* w2       = (const float*)d_in[11];
    const float* b2       = (const float*)d_in[12];
    float* out = (float*)d_out;

    int n = in_sizes[0];           // 50000
    int E = in_sizes[2] / 2;       // 800000
    int B = in_sizes[3];           // 8192
    int L = in_sizes[6] / (H * H); // 2

    const int* row = eidx;
    const int* col = eidx + E;

    float *zA, *zB, *agg, *deginv;
    int *count, *cursor, *offsets, *csr;
    cudaGetSymbolAddress((void**)&zA,      g_zA);
    cudaGetSymbolAddress((void**)&zB,      g_zB);
    cudaGetSymbolAddress((void**)&agg,     g_agg);
    cudaGetSymbolAddress((void**)&deginv,  g_deginv);
    cudaGetSymbolAddress((void**)&count,   g_count);
    cudaGetSymbolAddress((void**)&cursor,  g_cursor);
    cudaGetSymbolAddress((void**)&offsets, g_offsets);
    cudaGetSymbolAddress((void**)&csr,     g_csr_src);

    size_t gemm_smem = (size_t)(16384 + 16384 + 2 * GEMM_BM * LDA_S) * sizeof(float);
    size_t mlp_smem  = (size_t)(32768 + 256) * sizeof(float);
    cudaFuncSetAttribute(gemm_kernel, cudaFuncAttributeMaxDynamicSharedMemorySize, (int)gemm_smem);
    cudaFuncSetAttribute(mlp_kernel,  cudaFuncAttributeMaxDynamicSharedMemorySize, (int)mlp_smem);

    // 1) structure build (done once; shared by both layers)
    zero_kernel<<<(n + 255) / 256, 256>>>(count, cursor, n);
    gather_kernel<<<(n * 32 + 255) / 256, 256>>>(x, node_emb, zA, n);
    count_kernel<<<(E + 255) / 256, 256>>>(row, col, count, E);
    scan_kernel<<<1, 1024>>>(count, offsets, deginv, n);
    scatter_kernel<<<(E + 255) / 256, 256>>>(row, col, offsets, cursor, csr, E);

    int spmm_grid = (n * 32 + 255) / 256;
    int gemm_grid = (n + GEMM_BM - 1) / GEMM_BM;

    // 2) GCN layers (ping-pong zA <-> zB)
    float* zin  = zA;
    float* zout = zB;
    for (int l = 0; l < L; l++) {
        spmm_kernel<<<spmm_grid, 256>>>(zin, agg, offsets, csr, deginv, n);
        gemm_kernel<<<gemm_grid, 256, gemm_smem>>>(agg, zin,
                                                   Wout + (size_t)l * H * H,
                                                   Wroot + (size_t)l * H * H,
                                                   bout + (size_t)l * H,
                                                   zout, n);
        float* t = zin; zin = zout; zout = t;
    }

    // 3) head (zin holds final node features)
    mlp_kernel<<<296, 128, mlp_smem>>>(zin, labels, w1, b1, w2, b2, out, B, out_size);
}

// round 2
// speedup vs baseline: 1.8241x; 1.8241x over previous
#include <cuda_runtime.h>
#include <cuda_bf16.h>
#include <cstdio>

#define N_MAX 50000
#define E_MAX 800000
#define H 128

// -------- scratch (device globals; no allocation allowed) --------
__device__ float g_zA[(size_t)N_MAX * H];
__device__ float g_zB[(size_t)N_MAX * H];
__device__ float g_agg[(size_t)N_MAX * H];
__device__ int   g_csr_src[E_MAX];
__device__ int   g_count[N_MAX];
__device__ int   g_cursor[N_MAX];
__device__ int   g_offsets[N_MAX + 1];
__device__ float g_deginv[N_MAX];
__device__ int   g_bsums[256];

// -------- small helpers --------
__device__ __forceinline__ unsigned f2tf32(float x) {
    unsigned u;
    asm("cvt.rna.tf32.f32 %0, %1;" : "=r"(u) : "f"(x));
    return u;
}

__device__ __forceinline__ void mma_tf32(float c[4], const unsigned a[4], const unsigned b[2]) {
    asm volatile(
        "mma.sync.aligned.m16n8k8.row.col.f32.tf32.tf32.f32 "
        "{%0,%1,%2,%3}, {%4,%5,%6,%7}, {%8,%9}, {%0,%1,%2,%3};\n"
        : "+f"(c[0]), "+f"(c[1]), "+f"(c[2]), "+f"(c[3])
        : "r"(a[0]), "r"(a[1]), "r"(a[2]), "r"(a[3]), "r"(b[0]), "r"(b[1]));
}

// -------- structure-build kernels --------

__global__ void zero_kernel(int* count, int* cursor, int n) {
    int i = blockIdx.x * blockDim.x + threadIdx.x;
    if (i < n) { count[i] = 0; cursor[i] = 0; }
}

__global__ void gather_kernel(const int* x, const float* node_emb, float* z, int n) {
    int idx = blockIdx.x * blockDim.x + threadIdx.x;
    if (idx >= n * 32) return;
    int node = idx >> 5;
    int l4   = idx & 31;
    int e = x[node];
    ((float4*)z)[(size_t)node * 32 + l4] = ((const float4*)node_emb)[(size_t)e * 32 + l4];
}

__global__ void count_kernel(const int* row, const int* col, int* count, int E) {
    int e = blockIdx.x * blockDim.x + threadIdx.x;
    if (e >= E) return;
    int r = row[e], c = col[e];
    if (r != c) atomicAdd(&count[c], 1);
}

// phase 1: per-256-block sums
__global__ void block_sum_kernel(const int* __restrict__ count, int* __restrict__ bsums, int n) {
    __shared__ int sw[8];
    int tid = threadIdx.x;
    int i = blockIdx.x * 256 + tid;
    int v = (i < n) ? count[i] : 0;
    #pragma unroll
    for (int off = 16; off; off >>= 1) v += __shfl_xor_sync(0xFFFFFFFFu, v, off);
    if ((tid & 31) == 0) sw[tid >> 5] = v;
    __syncthreads();
    if (tid == 0) {
        int s = 0;
        #pragma unroll
        for (int w = 0; w < 8; w++) s += sw[w];
        bsums[blockIdx.x] = s;
    }
}

// phase 2: exclusive scan of up to 256 block sums (single block); writes total
__global__ void scan_sums_kernel(int* bsums, int* total_out, int nb) {
    __shared__ int s[256];
    int tid = threadIdx.x;
    int v = (tid < nb) ? bsums[tid] : 0;
    s[tid] = v;
    __syncthreads();
    #pragma unroll
    for (int off = 1; off < 256; off <<= 1) {
        int t = (tid >= off) ? s[tid - off] : 0;
        __syncthreads();
        s[tid] += t;
        __syncthreads();
    }
    if (tid < nb) bsums[tid] = s[tid] - v;   // exclusive
    if (tid == 255) *total_out = s[255];
}

// phase 3: per-block exclusive rescan + global block offset; also deg_inv
__global__ void final_scan_kernel(const int* __restrict__ count, const int* __restrict__ bsums,
                                  int* __restrict__ offsets, float* __restrict__ deg_inv, int n) {
    __shared__ int sw[8];
    __shared__ int woff[8];
    int tid = threadIdx.x;
    int lane = tid & 31, warp = tid >> 5;
    int i = blockIdx.x * 256 + tid;
    int v = (i < n) ? count[i] : 0;
    int x = v;
    #pragma unroll
    for (int off = 1; off < 32; off <<= 1) {
        int t = __shfl_up_sync(0xFFFFFFFFu, x, off);
        if (lane >= off) x += t;
    }
    if (lane == 31) sw[warp] = x;
    __syncthreads();
    if (tid == 0) {
        int acc = 0;
        #pragma unroll
        for (int w = 0; w < 8; w++) { woff[w] = acc; acc += sw[w]; }
    }
    __syncthreads();
    if (i < n) {
        offsets[i] = (x - v) + woff[warp] + bsums[blockIdx.x];
        deg_inv[i] = 1.0f / (float)(v + 1);
    }
}

__global__ void scatter_kernel(const int* row, const int* col, const int* offsets,
                               int* cursor, int* csr_src, int E) {
    int e = blockIdx.x * blockDim.x + threadIdx.x;
    if (e >= E) return;
    int r = row[e], c = col[e];
    if (r != c) {
        int p = atomicAdd(&cursor[c], 1);
        csr_src[offsets[c] + p] = r;
    }
}

// -------- SpMM (warp per node) --------
__global__ void spmm_kernel(const float* __restrict__ z, float* __restrict__ agg,
                            const int* __restrict__ offsets, const int* __restrict__ csr_src,
                            const float* __restrict__ deg_inv, int n) {
    int warp = (blockIdx.x * blockDim.x + threadIdx.x) >> 5;
    int lane = threadIdx.x & 31;
    if (warp >= n) return;
    const float4* z4 = (const float4*)z;
    float4 acc = z4[(size_t)warp * 32 + lane];
    int s = offsets[warp], e = offsets[warp + 1];
    for (int i = s; i < e; i++) {
        int r = csr_src[i];
        float4 v = z4[(size_t)r * 32 + lane];
        acc.x += v.x; acc.y += v.y; acc.z += v.z; acc.w += v.w;
    }
    float di = deg_inv[warp];
    acc.x *= di; acc.y *= di; acc.z *= di; acc.w *= di;
    ((float4*)agg)[(size_t)warp * 32 + lane] = acc;
}

// -------- tensor-core fused GEMM:  out = relu([A|Z](n x 256) @ [Wout;Wroot](256x128) + b) --------
#define BM 128
#define BN 128
#define BK 32
#define LDA 36      // 32 + 4 pad (words)
#define LDB 132     // 128 + 4 pad (words)
#define AS_SZ (BM * LDA)   // 4608 words
#define WS_SZ (BK * LDB)   // 4224 words

__global__ __launch_bounds__(256, 1)
void gemm_tc(const float* __restrict__ A, const float* __restrict__ Z,
             const float* __restrict__ Wout, const float* __restrict__ Wroot,
             const float* __restrict__ bias, float* __restrict__ out, int n)
{
    extern __shared__ unsigned sm[];
    unsigned* Asb[2] = { sm,                sm + AS_SZ };
    unsigned* Wsb[2] = { sm + 2 * AS_SZ,    sm + 2 * AS_SZ + WS_SZ };

    const int tid  = threadIdx.x;
    const int lane = tid & 31;
    const int warp = tid >> 5;
    const int wm = (warp & 1) * 64;        // warp tile 64 x 32
    const int wn = (warp >> 1) * 32;
    const int gid = lane >> 2;
    const int tig = lane & 3;
    const int m0 = blockIdx.x * BM;

    float4 ra[4];
    float4 rw[4];

    auto load_chunk = [&](int kc) {
        const float* src = (kc < 4) ? A : Z;
        int kb = (kc & 3) * 32;
        #pragma unroll
        for (int i = 0; i < 4; i++) {
            int idx = tid + i * 256;
            int m = idx >> 3, c4 = idx & 7;
            if (m0 + m < n)
                ra[i] = *(const float4*)(src + (size_t)(m0 + m) * H + kb + c4 * 4);
            else
                ra[i] = make_float4(0.f, 0.f, 0.f, 0.f);
        }
        const float* w = (kc < 4) ? Wout : Wroot;
        #pragma unroll
        for (int i = 0; i < 4; i++) {
            int idx = tid + i * 256;
            int k = idx >> 5, c4 = idx & 31;
            rw[i] = *(const float4*)(w + (size_t)(kb + k) * H + c4 * 4);
        }
    };

    auto store_chunk = [&](unsigned* as, unsigned* ws) {
        #pragma unroll
        for (int i = 0; i < 4; i++) {
            int idx = tid + i * 256;
            int m = idx >> 3, c4 = idx & 7;
            unsigned* p = as + m * LDA + c4 * 4;
            p[0] = f2tf32(ra[i].x); p[1] = f2tf32(ra[i].y);
            p[2] = f2tf32(ra[i].z); p[3] = f2tf32(ra[i].w);
        }
        #pragma unroll
        for (int i = 0; i < 4; i++) {
            int idx = tid + i * 256;
            int k = idx >> 5, c4 = idx & 31;
            unsigned* p = ws + k * LDB + c4 * 4;
            p[0] = f2tf32(rw[i].x); p[1] = f2tf32(rw[i].y);
            p[2] = f2tf32(rw[i].z); p[3] = f2tf32(rw[i].w);
        }
    };

    float c[4][4][4];
    #pragma unroll
    for (int i = 0; i < 4; i++)
        #pragma unroll
        for (int j = 0; j < 4; j++)
            #pragma unroll
            for (int q = 0; q < 4; q++) c[i][j][q] = 0.f;

    load_chunk(0);
    store_chunk(Asb[0], Wsb[0]);
    __syncthreads();

    int p = 0;
    for (int kc = 0; kc < 8; kc++) {
        if (kc < 7) load_chunk(kc + 1);

        unsigned* as = Asb[p];
        unsigned* ws = Wsb[p];
        #pragma unroll
        for (int k0 = 0; k0 < 32; k0 += 8) {
            unsigned af[4][4], bf[4][2];
            #pragma unroll
            for (int i = 0; i < 4; i++) {
                int r0 = (wm + 16 * i + gid) * LDA;
                int r1 = (wm + 16 * i + 8 + gid) * LDA;
                af[i][0] = as[r0 + k0 + tig];
                af[i][1] = as[r1 + k0 + tig];
                af[i][2] = as[r0 + k0 + tig + 4];
                af[i][3] = as[r1 + k0 + tig + 4];
            }
            #pragma unroll
            for (int j = 0; j < 4; j++) {
                bf[j][0] = ws[(k0 + tig) * LDB + wn + 8 * j + gid];
                bf[j][1] = ws[(k0 + tig + 4) * LDB + wn + 8 * j + gid];
            }
            #pragma unroll
            for (int i = 0; i < 4; i++)
                #pragma unroll
                for (int j = 0; j < 4; j++)
                    mma_tf32(c[i][j], af[i], bf[j]);
        }

        __syncthreads();
        if (kc < 7) {
            store_chunk(Asb[p ^ 1], Wsb[p ^ 1]);
            p ^= 1;
            __syncthreads();
        }
    }

    // epilogue: bias + relu, float2 stores
    #pragma unroll
    for (int j = 0; j < 4; j++) {
        int col = wn + 8 * j + 2 * tig;
        float b0 = bias[col], b1 = bias[col + 1];
        #pragma unroll
        for (int i = 0; i < 4; i++) {
            int r0 = m0 + wm + 16 * i + gid;
            if (r0 < n) {
                float2 o;
                o.x = fmaxf(c[i][j][0] + b0, 0.f);
                o.y = fmaxf(c[i][j][1] + b1, 0.f);
                *(float2*)&out[(size_t)r0 * H + col] = o;
            }
            if (r0 + 8 < n) {
                float2 o;
                o.x = fmaxf(c[i][j][2] + b0, 0.f);
                o.y = fmaxf(c[i][j][3] + b1, 0.f);
                *(float2*)&out[(size_t)(r0 + 8) * H + col] = o;
            }
        }
    }
}

// -------- MLP head --------
__global__ __launch_bounds__(128, 1)
void mlp_kernel(const float* __restrict__ z, const int* __restrict__ labels,
                const float* __restrict__ w1, const float* __restrict__ b1,
                const float* __restrict__ w2, const float* __restrict__ b2,
                float* __restrict__ out, int bsz, int out_size) {
    extern __shared__ float smem[];
    float* w1s = smem;          // 256*128
    float* ge  = smem + 32768;  // 256
    __shared__ float red[4];
    int tid = threadIdx.x;
    for (int i = tid; i < 8192; i += 128)
        ((float4*)w1s)[i] = ((const float4*)w1)[i];
    float b1v = b1[tid];
    float w2v = w2[tid];
    float b2v = b2[0];
    __syncthreads();

    for (int r = blockIdx.x; r < bsz; r += gridDim.x) {
        ge[tid]       = z[(size_t)r * H + tid];
        ge[128 + tid] = z[(size_t)(bsz + r) * H + tid];
        __syncthreads();
        float h = b1v;
        #pragma unroll 8
        for (int k = 0; k < 256; k++)
            h += ge[k] * w1s[k * 128 + tid];
        h = fmaxf(h, 0.f) * w2v;
        #pragma unroll
        for (int off = 16; off; off >>= 1)
            h += __shfl_xor_sync(0xFFFFFFFFu, h, off);
        if ((tid & 31) == 0) red[tid >> 5] = h;
        __syncthreads();
        if (tid == 0) {
            float pv = red[0] + red[1] + red[2] + red[3] + b2v;
            out[r] = pv;
            if (out_size >= 2 * bsz) out[bsz + r] = (float)labels[r];
        }
        __syncthreads();
    }
}

// -------- host --------
extern "C" void kernel_launch(void* const* d_in, const int* in_sizes, int n_in,
                              void* d_out, int out_size) {
    const int*   x        = (const int*)d_in[0];
    const int*   eidx     = (const int*)d_in[2];
    const int*   labels   = (const int*)d_in[3];
    const float* node_emb = (const float*)d_in[4];
    const float* Wout     = (const float*)d_in[6];
    const float* bout     = (const float*)d_in[7];
    const float* Wroot    = (const float*)d_in[8];
    const float* w1       = (const float*)d_in[9];
    const float* b1       = (const float*)d_in[10];
    const float* w2       = (const float*)d_in[11];
    const float* b2       = (const float*)d_in[12];
    float* out = (float*)d_out;

    int n = in_sizes[0];
    int E = in_sizes[2] / 2;
    int B = in_sizes[3];
    int L = in_sizes[6] / (H * H);

    const int* row = eidx;
    const int* col = eidx + E;

    float *zA, *zB, *agg, *deginv;
    int *count, *cursor, *offsets, *csr, *bsums;
    cudaGetSymbolAddress((void**)&zA,      g_zA);
    cudaGetSymbolAddress((void**)&zB,      g_zB);
    cudaGetSymbolAddress((void**)&agg,     g_agg);
    cudaGetSymbolAddress((void**)&deginv,  g_deginv);
    cudaGetSymbolAddress((void**)&count,   g_count);
    cudaGetSymbolAddress((void**)&cursor,  g_cursor);
    cudaGetSymbolAddress((void**)&offsets, g_offsets);
    cudaGetSymbolAddress((void**)&csr,     g_csr_src);
    cudaGetSymbolAddress((void**)&bsums,   g_bsums);

    size_t gemm_smem = (size_t)(2 * (AS_SZ + WS_SZ)) * sizeof(unsigned); // 70656 B
    size_t mlp_smem  = (size_t)(32768 + 256) * sizeof(float);
    cudaFuncSetAttribute(gemm_tc,    cudaFuncAttributeMaxDynamicSharedMemorySize, (int)gemm_smem);
    cudaFuncSetAttribute(mlp_kernel, cudaFuncAttributeMaxDynamicSharedMemorySize, (int)mlp_smem);

    int nb = (n + 255) / 256;   // 196 <= 256

    // 1) structure build
    zero_kernel<<<(n + 255) / 256, 256>>>(count, cursor, n);
    gather_kernel<<<(n * 32 + 255) / 256, 256>>>(x, node_emb, zA, n);
    count_kernel<<<(E + 255) / 256, 256>>>(row, col, count, E);
    block_sum_kernel<<<nb, 256>>>(count, bsums, n);
    scan_sums_kernel<<<1, 256>>>(bsums, offsets + n, nb);
    final_scan_kernel<<<nb, 256>>>(count, bsums, offsets, deginv, n);
    scatter_kernel<<<(E + 255) / 256, 256>>>(row, col, offsets, cursor, csr, E);

    int spmm_grid = (n * 32 + 255) / 256;
    int gemm_grid = (n + BM - 1) / BM;

    // 2) GCN layers
    float* zin  = zA;
    float* zout = zB;
    for (int l = 0; l < L; l++) {
        spmm_kernel<<<spmm_grid, 256>>>(zin, agg, offsets, csr, deginv, n);
        gemm_tc<<<gemm_grid, 256, gemm_smem>>>(agg, zin,
                                               Wout + (size_t)l * H * H,
                                               Wroot + (size_t)l * H * H,
                                               bout + (size_t)l * H,
                                               zout, n);
        float* t = zin; zin = zout; zout = t;
    }

    // 3) head
    mlp_kernel<<<296, 128, mlp_smem>>>(zin, labels, w1, b1, w2, b2, out, B, out_size);
}